// round 15
// baseline (speedup 1.0000x reference)
#include <cuda_runtime.h>
#include <cuda_fp16.h>
#include <math.h>
#include <stdint.h>

// ---------------------------------------------------------------------------
// Problem constants (fixed shapes)
// ---------------------------------------------------------------------------
#define Bb     2
#define Ll     2048
#define Dm     1024
#define Hh     32
#define Pp     64
#define Nn     128
#define KCONV  4
#define Ck     256
#define Nc     8          // Ll / Ck
#define Inter  2048
#define ConvD  2304
#define ProjD  4384
#define BL     (Bb * Ll)  // 4096

// ---------------------------------------------------------------------------
// Scratch (device globals; no dynamic allocation allowed)
// ---------------------------------------------------------------------------
__device__ float g_proj[(size_t)BL * ProjD];
__device__ float g_conv[(size_t)BL * ConvD];
__device__ float g_dtv[(size_t)BL * Hh];
__device__ float g_acum[(size_t)Bb * Nc * Hh * Ck];
__device__ float g_gm[(size_t)Bb * Nc * Ck * Ck];
__device__ float g_y[(size_t)BL * Inter];
__device__ float g_states[(size_t)Bb * Nc * Hh * Pp * Nn];
__device__ float g_prev[(size_t)Bb * Nc * Hh * Pp * Nn];

// fp16 buffers
__device__ __half g_Ah[(size_t)BL * Inter];
__device__ __half g_Bh[(size_t)ProjD * Dm];

__device__ __forceinline__ float siluf(float x) { return x / (1.f + expf(-x)); }

__device__ __forceinline__ float4 ldg4(const float* p) {
    return *reinterpret_cast<const float4*>(p);
}

// ---------------------------------------------------------------------------
// PTX helpers
// ---------------------------------------------------------------------------
__device__ __forceinline__ unsigned su32(const void* p) {
    return (unsigned)__cvta_generic_to_shared(p);
}

__device__ __forceinline__ void cp16(unsigned dst, const void* src, bool ok) {
    int sz = ok ? 16 : 0;
    asm volatile("cp.async.cg.shared.global [%0], [%1], 16, %2;\n"
                 :: "r"(dst), "l"(src), "r"(sz));
}

__device__ __forceinline__ void ldsm4(unsigned& r0, unsigned& r1, unsigned& r2, unsigned& r3,
                                      unsigned addr) {
    asm volatile("ldmatrix.sync.aligned.m8n8.x4.shared.b16 {%0,%1,%2,%3}, [%4];"
                 : "=r"(r0), "=r"(r1), "=r"(r2), "=r"(r3) : "r"(addr));
}

__device__ __forceinline__ void mma16816(float* c, const unsigned* a, const unsigned* b) {
    asm volatile(
        "mma.sync.aligned.m16n8k16.row.col.f32.f16.f16.f32 "
        "{%0,%1,%2,%3}, {%4,%5,%6,%7}, {%8,%9}, {%0,%1,%2,%3};"
        : "+f"(c[0]), "+f"(c[1]), "+f"(c[2]), "+f"(c[3])
        : "r"(a[0]), "r"(a[1]), "r"(a[2]), "r"(a[3]), "r"(b[0]), "r"(b[1]));
}

// ---------------------------------------------------------------------------
// Tensor-core fp16 GEMM, 1-pass: C = Ah*Bh, fp32 accum. (proven R10/R11)
// ---------------------------------------------------------------------------
#define GEMM_SMEM (2 * 36864)

struct Frags {
    unsigned ah[4][4];
    unsigned bh[4][2];
};

__device__ __forceinline__ void load_frags(Frags& F, unsigned stg, int ks,
                                           int wm, int wn, int lane) {
    const int rA = lane & 15;
    const int cB = ((lane >> 4) << 4);
    const unsigned colb = (unsigned)(ks * 32 + cB);
#pragma unroll
    for (int mf = 0; mf < 4; mf++) {
        unsigned ra = stg + (wm * 64 + mf * 16 + rA) * 144 + colb;
        ldsm4(F.ah[mf][0], F.ah[mf][1], F.ah[mf][2], F.ah[mf][3], ra);
    }
#pragma unroll
    for (int nf2 = 0; nf2 < 2; nf2++) {
        unsigned rb = stg + 18432 + (wn * 32 + nf2 * 16 + rA) * 144 + colb;
        unsigned t0, t1, t2, t3;
        ldsm4(t0, t1, t2, t3, rb);
        F.bh[nf2 * 2][0] = t0; F.bh[nf2 * 2][1] = t2;
        F.bh[nf2 * 2 + 1][0] = t1; F.bh[nf2 * 2 + 1][1] = t3;
    }
}

__device__ __forceinline__ void gemm_core(const __half* __restrict__ Ah,
                                          const __half* __restrict__ Bh,
                                          float* __restrict__ C,
                                          int M, int N, int K) {
    extern __shared__ char dyn[];
    const unsigned sbase = su32(dyn);
    const int tid = threadIdx.x;
    const int lane = tid & 31;
    const int warp = tid >> 5;
    const int wm = warp >> 2;
    const int wn = warp & 3;
    const int m0 = blockIdx.y * 128;
    const int n0 = blockIdx.x * 128;
    const int KB = K >> 6;

    float acc[4][4][4];
#pragma unroll
    for (int a = 0; a < 4; a++)
#pragma unroll
        for (int b = 0; b < 4; b++)
#pragma unroll
            for (int c = 0; c < 4; c++) acc[a][b][c] = 0.f;

    auto issue = [&](int kc, int st) {
        unsigned stg = sbase + st * 36864;
#pragma unroll
        for (int i = 0; i < 8; i++) {
            int q = tid + (i << 8);
            int mat = q >> 10;
            int r = (q >> 3) & 127;
            int c16 = q & 7;
            const __half* base = mat ? Bh : Ah;
            int gr = (mat ? n0 : m0) + r;
            bool ok = gr < (mat ? N : M);
            if (!ok) gr = (mat ? N : M) - 1;
            const void* src = base + (size_t)gr * K + (kc << 6) + (c16 << 3);
            unsigned dst = stg + mat * 18432 + r * 144 + (c16 << 4);
            cp16(dst, src, ok);
        }
        asm volatile("cp.async.commit_group;\n");
    };

    issue(0, 0);
    if (KB > 1) issue(1, 1);

    Frags F[2];

    for (int kb = 0; kb < KB; kb++) {
        int st = kb & 1;
        if (kb + 1 < KB) asm volatile("cp.async.wait_group 1;\n");
        else             asm volatile("cp.async.wait_group 0;\n");
        __syncthreads();
        unsigned stg = sbase + st * 36864;

        load_frags(F[0], stg, 0, wm, wn, lane);
#pragma unroll
        for (int ks = 0; ks < 4; ks++) {
            if (ks < 3) load_frags(F[(ks + 1) & 1], stg, ks + 1, wm, wn, lane);
            Frags& f = F[ks & 1];
#pragma unroll
            for (int mf = 0; mf < 4; mf++)
#pragma unroll
                for (int nf = 0; nf < 4; nf++)
                    mma16816(acc[mf][nf], f.ah[mf], f.bh[nf]);
        }
        __syncthreads();
        if (kb + 2 < KB) issue(kb + 2, st);
    }

    int g4 = lane >> 2, t4 = lane & 3;
#pragma unroll
    for (int mf = 0; mf < 4; mf++) {
        int r0 = m0 + wm * 64 + mf * 16 + g4;
#pragma unroll
        for (int nf = 0; nf < 4; nf++) {
            int cg = n0 + wn * 32 + nf * 8 + t4 * 2;
            if (cg < N) {
                float* p0 = C + (size_t)r0 * N + cg;
                p0[0] = acc[mf][nf][0];
                p0[1] = acc[mf][nf][1];
                float* p1 = p0 + (size_t)8 * N;
                p1[0] = acc[mf][nf][2];
                p1[1] = acc[mf][nf][3];
            }
        }
    }
}

__global__ __launch_bounds__(256) void gemm_in_kernel() {
    gemm_core(g_Ah, g_Bh, g_proj, BL, ProjD, Dm);
}

__global__ __launch_bounds__(256) void gemm_out_kernel(float* __restrict__ out) {
    gemm_core(g_Ah, g_Bh, out, BL, Dm, Inter);
}

// ---------------------------------------------------------------------------
// fp16 conversions
// ---------------------------------------------------------------------------
__global__ void round_x_kernel(const float* __restrict__ in, int n) {
    int i = blockIdx.x * blockDim.x + threadIdx.x;
    if (i >= n) return;
    g_Ah[i] = __float2half(in[i]);
}

__global__ void round_w_kernel(const float* __restrict__ in, int n) {
    int i = blockIdx.x * blockDim.x + threadIdx.x;
    if (i >= n) return;
    g_Bh[i] = __float2half(in[i]);
}

// ---------------------------------------------------------------------------
// Depthwise causal conv1d + SiLU (sliding window, 32 positions/thread)
// ---------------------------------------------------------------------------
__global__ __launch_bounds__(256) void conv_silu_kernel(const float* __restrict__ cw,
                                                        const float* __restrict__ cb) {
    int ch = blockIdx.x * 256 + threadIdx.x;
    int l0 = blockIdx.y * 32;
    int b  = blockIdx.z;
    const float* col = g_proj + (size_t)b * Ll * ProjD + Inter + ch;
    float w0 = cw[ch * KCONV + 0];
    float w1 = cw[ch * KCONV + 1];
    float w2 = cw[ch * KCONV + 2];
    float w3 = cw[ch * KCONV + 3];
    float bias = cb[ch];
    float xm3 = (l0 >= 3) ? col[(size_t)(l0 - 3) * ProjD] : 0.f;
    float xm2 = (l0 >= 2) ? col[(size_t)(l0 - 2) * ProjD] : 0.f;
    float xm1 = (l0 >= 1) ? col[(size_t)(l0 - 1) * ProjD] : 0.f;
    float* outp = g_conv + (size_t)(b * Ll + l0) * ConvD + ch;
#pragma unroll 4
    for (int i = 0; i < 32; i++) {
        float x0 = col[(size_t)(l0 + i) * ProjD];
        float acc = bias + w0 * xm3 + w1 * xm2 + w2 * xm1 + w3 * x0;
        outp[(size_t)i * ConvD] = siluf(acc);
        xm3 = xm2; xm2 = xm1; xm1 = x0;
    }
}

// ---------------------------------------------------------------------------
// Per-chunk inclusive cumsum of dt * A with fused softplus
// ---------------------------------------------------------------------------
__global__ void acum_kernel(const float* __restrict__ A_log,
                            const float* __restrict__ dt_bias) {
    int blk = blockIdx.x;
    int h = blk % Hh;
    int bc = blk / Hh;
    int b = bc / Nc, c = bc % Nc;
    int t = threadIdx.x;
    float A = -expf(A_log[h]);
    int bl = b * Ll + c * Ck + t;
    float raw = g_proj[(size_t)bl * ProjD + Inter + ConvD + h] + dt_bias[h];
    float dt = (raw > 20.f) ? raw : log1pf(expf(raw));
    g_dtv[(size_t)bl * Hh + h] = dt;
    float v = dt * A;
    __shared__ float s[Ck];
    s[t] = v;
    __syncthreads();
    for (int off = 1; off < Ck; off <<= 1) {
        float x = (t >= off) ? s[t - off] : 0.f;
        __syncthreads();
        s[t] += x;
        __syncthreads();
    }
    g_acum[(size_t)blk * Ck + t] = s[t];
}

// ---------------------------------------------------------------------------
// Gm[s,z] = sum_n C[s,n] * B[z,n] per (b,c), lower triangle (fp32, R11)
// ---------------------------------------------------------------------------
__global__ __launch_bounds__(256) void gm_kernel() {
    int bc = blockIdx.x;
    int sT = blockIdx.y, zT = blockIdx.z;
    if (zT > sT) return;
    int b = bc / Nc, c = bc % Nc;
    int rowbase = b * Ll + c * Ck;
    __shared__ __align__(16) float Cs[16][68];
    __shared__ __align__(16) float Bs[16][68];
    int tid = threadIdx.x;
    int ty = tid >> 4, tx = tid & 15;
    float acc[4][4];
#pragma unroll
    for (int i = 0; i < 4; i++)
#pragma unroll
        for (int j = 0; j < 4; j++) acc[i][j] = 0.f;

    int lrow = tid >> 2;
    int lcol = (tid & 3) * 4;

    for (int n0 = 0; n0 < Nn; n0 += 16) {
        float4 vc = ldg4(g_conv + (size_t)(rowbase + sT * 64 + lrow) * ConvD + Inter + Nn + n0 + lcol);
        float4 vb = ldg4(g_conv + (size_t)(rowbase + zT * 64 + lrow) * ConvD + Inter + n0 + lcol);
        Cs[lcol + 0][lrow] = vc.x; Cs[lcol + 1][lrow] = vc.y;
        Cs[lcol + 2][lrow] = vc.z; Cs[lcol + 3][lrow] = vc.w;
        Bs[lcol + 0][lrow] = vb.x; Bs[lcol + 1][lrow] = vb.y;
        Bs[lcol + 2][lrow] = vb.z; Bs[lcol + 3][lrow] = vb.w;
        __syncthreads();
#pragma unroll
        for (int kk = 0; kk < 16; kk++) {
            float4 rc = *(const float4*)&Cs[kk][ty * 4];
            float4 rb = *(const float4*)&Bs[kk][tx * 4];
            float rcv[4] = {rc.x, rc.y, rc.z, rc.w};
            float rbv[4] = {rb.x, rb.y, rb.z, rb.w};
#pragma unroll
            for (int i = 0; i < 4; i++)
#pragma unroll
                for (int j = 0; j < 4; j++) acc[i][j] += rcv[i] * rbv[j];
        }
        __syncthreads();
    }
#pragma unroll
    for (int i = 0; i < 4; i++) {
        int sg = sT * 64 + ty * 4 + i;
        float* pg = g_gm + ((size_t)bc * Ck + sg) * Ck + zT * 64 + tx * 4;
        *reinterpret_cast<float4*>(pg) = make_float4(acc[i][0], acc[i][1], acc[i][2], acc[i][3]);
    }
}

// ---------------------------------------------------------------------------
// states — fp16 mma: out[p=64][n=128] = sum_l H[p,l]*B[n,l], K=256 in 4 chunks.
// 8 warps = 4(m p-tiles of 16) x 2(n halves of 64). Coalesced float2 epilogue.
// ---------------------------------------------------------------------------
__global__ __launch_bounds__(256) void states_kernel() {
    int bc = blockIdx.x, h = blockIdx.y;
    int b = bc / Nc, c = bc % Nc;
    int tid = threadIdx.x;
    int lane = tid & 31;
    int warp = tid >> 5;
    int wm = warp >> 1;   // 0..3
    int wn = warp & 1;    // 0..1

    __shared__ __align__(16) __half Hsh[64][72];    // [p][l]
    __shared__ __align__(16) __half Bsh[128][72];   // [n][l]

    const float* acumC = g_acum + ((size_t)bc * Hh + h) * Ck;
    float aLast = acumC[Ck - 1];
    int rowbase = b * Ll + c * Ck;

    float acc[8][4];
#pragma unroll
    for (int i = 0; i < 8; i++)
#pragma unroll
        for (int j = 0; j < 4; j++) acc[i][j] = 0.f;

    const unsigned hbv = su32(Hsh);
    const unsigned bbv = su32(Bsh);
    const int rA = lane & 15;
    const int cBy = (lane >> 4) << 4;

    for (int lc = 0; lc < 4; lc++) {
        {
            // Hsh[p][l] = hs[l][p] * dt[l] * exp(aLast - acum[l]) (transposed)
            int ll = tid >> 2;
            int p0 = (tid & 3) * 16;
            int l = rowbase + lc * 64 + ll;
            float w = g_dtv[(size_t)l * Hh + h] * expf(aLast - acumC[lc * 64 + ll]);
            const float* ph = g_conv + (size_t)l * ConvD + h * Pp + p0;
#pragma unroll
            for (int u = 0; u < 4; u++) {
                float4 v = ldg4(ph + u * 4);
                Hsh[p0 + u * 4 + 0][ll] = __float2half(v.x * w);
                Hsh[p0 + u * 4 + 1][ll] = __float2half(v.y * w);
                Hsh[p0 + u * 4 + 2][ll] = __float2half(v.z * w);
                Hsh[p0 + u * 4 + 3][ll] = __float2half(v.w * w);
            }
        }
#pragma unroll
        for (int i = 0; i < 8; i++) {
            // Bsh[n][l] = B[l][n] (transposed)
            int q = tid + (i << 8);
            int ll = q >> 5;
            int n4 = (q & 31) * 4;
            float4 v = ldg4(g_conv + (size_t)(rowbase + lc * 64 + ll) * ConvD + Inter + n4);
            Bsh[n4 + 0][ll] = __float2half(v.x);
            Bsh[n4 + 1][ll] = __float2half(v.y);
            Bsh[n4 + 2][ll] = __float2half(v.z);
            Bsh[n4 + 3][ll] = __float2half(v.w);
        }
        __syncthreads();
#pragma unroll
        for (int ks = 0; ks < 4; ks++) {
            unsigned colb = (unsigned)(ks * 32 + cBy);
            unsigned a[4];
            ldsm4(a[0], a[1], a[2], a[3], hbv + (wm * 16 + rA) * 144 + colb);
            unsigned bfr[8][2];
#pragma unroll
            for (int nf2 = 0; nf2 < 4; nf2++) {
                unsigned rb = bbv + (wn * 64 + nf2 * 16 + rA) * 144 + colb;
                unsigned t0, t1, t2, t3;
                ldsm4(t0, t1, t2, t3, rb);
                bfr[nf2 * 2][0] = t0; bfr[nf2 * 2][1] = t2;
                bfr[nf2 * 2 + 1][0] = t1; bfr[nf2 * 2 + 1][1] = t3;
            }
#pragma unroll
            for (int nf = 0; nf < 8; nf++)
                mma16816(acc[nf], a, bfr[nf]);
        }
        __syncthreads();
    }

    float* ps = g_states + ((size_t)bc * Hh + h) * Pp * Nn;
    int g4 = lane >> 2, t4 = lane & 3;
    int p0r = wm * 16 + g4;
#pragma unroll
    for (int nf = 0; nf < 8; nf++) {
        int n = wn * 64 + nf * 8 + t4 * 2;
        *(float2*)(ps + (size_t)p0r * Nn + n) = make_float2(acc[nf][0], acc[nf][1]);
        *(float2*)(ps + (size_t)(p0r + 8) * Nn + n) = make_float2(acc[nf][2], acc[nf][3]);
    }
}

// ---------------------------------------------------------------------------
// Inter-chunk recurrence
// ---------------------------------------------------------------------------
__global__ void prev_kernel() {
    int idx = blockIdx.x * blockDim.x + threadIdx.x;
    if (idx >= Bb * Hh * Pp * Nn) return;
    int n = idx % Nn;
    int p = (idx / Nn) % Pp;
    int h = (idx / (Nn * Pp)) % Hh;
    int b = idx / (Nn * Pp * Hh);
    float r = 0.f;
    for (int c = 0; c < Nc; c++) {
        size_t off = (((size_t)(b * Nc + c) * Hh + h) * Pp + p) * Nn + n;
        g_prev[off] = r;
        float zl = g_acum[((size_t)(b * Nc + c) * Hh + h) * Ck + (Ck - 1)];
        r = g_states[off] + expf(zl) * r;
    }
}

// ---------------------------------------------------------------------------
// FUSED Y_diag + Y_off + D residual — tensor-core version (R14, proven).
// ---------------------------------------------------------------------------
__global__ __launch_bounds__(256) void ydiag_yoff_kernel(const float* __restrict__ Dv) {
    int bc = blockIdx.x;
    int h = blockIdx.y;
    int sT = blockIdx.z;
    int b = bc / Nc, c = bc % Nc;
    int tid = threadIdx.x;
    int lane = tid & 31;
    int warp = tid >> 5;
    int wm = warp >> 1;     // 0..3 (16 rows each)
    int wn = warp & 1;      // 0..1 (32 cols each)

    __shared__ __align__(16) char sb[34816];
    __half* Msh = (__half*)sb;            // [64][72]  A: [s][z]
    __half* Hsh = (__half*)(sb + 9216);   // [64][72]  B: [p][z]
    __half* Csh = (__half*)sb;            // [64][136] A: [l][n]
    __half* Psh = (__half*)(sb + 17408);  // [64][136] B: [p][n]
    __shared__ float sAc[64], zAc[64], ezs[64];

    const float* acumC = g_acum + ((size_t)bc * Hh + h) * Ck;
    if (tid < 64) sAc[tid] = acumC[sT * 64 + tid];
    int rowbase = b * Ll + c * Ck;
    int lbase = rowbase + sT * 64;

    const unsigned mbase = su32(Msh);
    const unsigned hbase = su32(Hsh);
    const int rA = lane & 15;
    const int cBy = (lane >> 4) << 4;

    float accd[4][4];
#pragma unroll
    for (int i = 0; i < 4; i++)
#pragma unroll
        for (int j = 0; j < 4; j++) accd[i][j] = 0.f;

    for (int zT = 0; zT <= sT; zT++) {
        float M = acumC[zT * 64 + 63];
        if (tid < 64) {
            float az = acumC[zT * 64 + tid];
            zAc[tid] = az;
            ezs[tid] = expf(M - az);
        }
        {
            int zz = tid >> 2;
            int p0 = (tid & 3) * 16;
            int l = rowbase + zT * 64 + zz;
            float d = g_dtv[(size_t)l * Hh + h];
            const float* ph = g_conv + (size_t)l * ConvD + h * Pp + p0;
#pragma unroll
            for (int u = 0; u < 4; u++) {
                float4 v = ldg4(ph + u * 4);
                Hsh[(p0 + u * 4 + 0) * 72 + zz] = __float2half(v.x * d);
                Hsh[(p0 + u * 4 + 1) * 72 + zz] = __float2half(v.y * d);
                Hsh[(p0 + u * 4 + 2) * 72 + zz] = __float2half(v.z * d);
                Hsh[(p0 + u * 4 + 3) * 72 + zz] = __float2half(v.w * d);
            }
        }
        __syncthreads();
        {
            int zz4 = (tid & 15) * 4;
            int ss4 = (tid >> 4) * 4;
            if (zT < sT) {
#pragma unroll
                for (int a = 0; a < 4; a++) {
                    int ss = ss4 + a;
                    int sg = sT * 64 + ss;
                    float es = expf(sAc[ss] - M);
                    float4 g = ldg4(g_gm + ((size_t)bc * Ck + sg) * Ck + zT * 64 + zz4);
                    float m0 = g.x * ezs[zz4 + 0] * es;
                    float m1 = g.y * ezs[zz4 + 1] * es;
                    float m2 = g.z * ezs[zz4 + 2] * es;
                    float m3 = g.w * ezs[zz4 + 3] * es;
                    *(half2*)&Msh[ss * 72 + zz4]     = __floats2half2_rn(m0, m1);
                    *(half2*)&Msh[ss * 72 + zz4 + 2] = __floats2half2_rn(m2, m3);
                }
            } else {
#pragma unroll
                for (int a = 0; a < 4; a++) {
                    int ss = ss4 + a;
                    int sg = sT * 64 + ss;
                    float as = sAc[ss];
                    float4 g = ldg4(g_gm + ((size_t)bc * Ck + sg) * Ck + zT * 64 + zz4);
                    float gv[4] = {g.x, g.y, g.z, g.w};
                    float mv[4];
#pragma unroll
                    for (int q = 0; q < 4; q++) {
                        int zz = zz4 + q;
                        mv[q] = ((zT * 64 + zz) <= sg) ? gv[q] * expf(as - zAc[zz]) : 0.f;
                    }
                    *(half2*)&Msh[ss * 72 + zz4]     = __floats2half2_rn(mv[0], mv[1]);
                    *(half2*)&Msh[ss * 72 + zz4 + 2] = __floats2half2_rn(mv[2], mv[3]);
                }
            }
        }
        __syncthreads();
#pragma unroll
        for (int ks = 0; ks < 4; ks++) {
            unsigned colb = (unsigned)(ks * 32 + cBy);
            unsigned a[4];
            ldsm4(a[0], a[1], a[2], a[3], mbase + (wm * 16 + rA) * 144 + colb);
            unsigned bh[4][2];
#pragma unroll
            for (int nf2 = 0; nf2 < 2; nf2++) {
                unsigned rb = hbase + (wn * 32 + nf2 * 16 + rA) * 144 + colb;
                unsigned t0, t1, t2, t3;
                ldsm4(t0, t1, t2, t3, rb);
                bh[nf2 * 2][0] = t0; bh[nf2 * 2][1] = t2;
                bh[nf2 * 2 + 1][0] = t1; bh[nf2 * 2 + 1][1] = t3;
            }
#pragma unroll
            for (int nf = 0; nf < 4; nf++)
                mma16816(accd[nf], a, bh[nf]);
        }
        __syncthreads();
    }

    float acco[4][4];
#pragma unroll
    for (int i = 0; i < 4; i++)
#pragma unroll
        for (int j = 0; j < 4; j++) acco[i][j] = 0.f;

    const float* pprev = g_prev + ((size_t)bc * Hh + h) * Pp * Nn;
#pragma unroll
    for (int i = 0; i < 8; i++) {
        int q = tid + (i << 8);
        int row = q >> 5;
        int c4 = (q & 31) * 4;
        float4 vc = ldg4(g_conv + (size_t)(lbase + row) * ConvD + Inter + Nn + c4);
        *(half2*)&Csh[row * 136 + c4]     = __floats2half2_rn(vc.x, vc.y);
        *(half2*)&Csh[row * 136 + c4 + 2] = __floats2half2_rn(vc.z, vc.w);
        float4 vp = ldg4(pprev + (size_t)row * Nn + c4);
        *(half2*)&Psh[row * 136 + c4]     = __floats2half2_rn(vp.x, vp.y);
        *(half2*)&Psh[row * 136 + c4 + 2] = __floats2half2_rn(vp.z, vp.w);
    }
    __syncthreads();
    const unsigned cbase2 = su32(Csh);
    const unsigned pbase2 = su32(Psh);
#pragma unroll
    for (int ks = 0; ks < 8; ks++) {
        unsigned colb = (unsigned)(ks * 32 + cBy);
        unsigned a[4];
        ldsm4(a[0], a[1], a[2], a[3], cbase2 + (wm * 16 + rA) * 272 + colb);
        unsigned bh[4][2];
#pragma unroll
        for (int nf2 = 0; nf2 < 2; nf2++) {
            unsigned rb = pbase2 + (wn * 32 + nf2 * 16 + rA) * 272 + colb;
            unsigned t0, t1, t2, t3;
            ldsm4(t0, t1, t2, t3, rb);
            bh[nf2 * 2][0] = t0; bh[nf2 * 2][1] = t2;
            bh[nf2 * 2 + 1][0] = t1; bh[nf2 * 2 + 1][1] = t3;
        }
#pragma unroll
        for (int nf = 0; nf < 4; nf++)
            mma16816(acco[nf], a, bh[nf]);
    }

    float Dh = Dv[h];
    int r0 = wm * 16 + (lane >> 2);
    int pb0 = wn * 32 + (lane & 3) * 2;
    float sd0 = expf(sAc[r0]);
    float sd1 = expf(sAc[r0 + 8]);
    int l0v = lbase + r0;
    int l1v = l0v + 8;
#pragma unroll
    for (int nf = 0; nf < 4; nf++) {
        int p = pb0 + nf * 8;
        float2 hv0 = *(const float2*)(g_conv + (size_t)l0v * ConvD + h * Pp + p);
        float2 o0;
        o0.x = accd[nf][0] + acco[nf][0] * sd0 + Dh * hv0.x;
        o0.y = accd[nf][1] + acco[nf][1] * sd0 + Dh * hv0.y;
        *(float2*)(g_y + (size_t)l0v * Inter + h * Pp + p) = o0;
        float2 hv1 = *(const float2*)(g_conv + (size_t)l1v * ConvD + h * Pp + p);
        float2 o1;
        o1.x = accd[nf][2] + acco[nf][2] * sd1 + Dh * hv1.x;
        o1.y = accd[nf][3] + acco[nf][3] * sd1 + Dh * hv1.y;
        *(float2*)(g_y + (size_t)l1v * Inter + h * Pp + p) = o1;
    }
}

// ---------------------------------------------------------------------------
// Gated RMSNorm; writes fp16-rounded y for the 1-pass out-proj
// ---------------------------------------------------------------------------
__global__ __launch_bounds__(256) void norm_kernel(const float* __restrict__ norm_w) {
    int row = blockIdx.x;
    int tid = threadIdx.x;
    const float* pg = g_proj + (size_t)row * ProjD;
    const float* py = g_y + (size_t)row * Inter;
    float f[8];
    float ss = 0.f;
#pragma unroll
    for (int u = 0; u < 8; u++) {
        int i = tid + u * 256;
        float g = pg[i];
        float v = py[i] * siluf(g);
        f[u] = v;
        ss += v * v;
    }
    __shared__ float red[8];
    int lane = tid & 31, wid = tid >> 5;
#pragma unroll
    for (int o = 16; o > 0; o >>= 1) ss += __shfl_xor_sync(0xffffffffu, ss, o);
    if (lane == 0) red[wid] = ss;
    __syncthreads();
    if (tid == 0) {
        float t = 0.f;
#pragma unroll
        for (int i = 0; i < 8; i++) t += red[i];
        red[0] = t;
    }
    __syncthreads();
    float rs = rsqrtf(red[0] / (float)Inter + 1e-6f);
#pragma unroll
    for (int u = 0; u < 8; u++) {
        int i = tid + u * 256;
        float v = f[u] * rs * norm_w[i];
        g_Ah[(size_t)row * Inter + i] = __float2half(v);
    }
}

// ---------------------------------------------------------------------------
// Launch
// ---------------------------------------------------------------------------
extern "C" void kernel_launch(void* const* d_in, const int* in_sizes, int n_in,
                              void* d_out, int out_size) {
    const float* x         = (const float*)d_in[0];
    const float* in_proj_w = (const float*)d_in[1];
    const float* conv_w    = (const float*)d_in[2];
    const float* conv_b    = (const float*)d_in[3];
    const float* dt_bias   = (const float*)d_in[4];
    const float* A_log     = (const float*)d_in[5];
    const float* Dv        = (const float*)d_in[6];
    const float* norm_w    = (const float*)d_in[7];
    const float* out_proj_w= (const float*)d_in[8];
    float* out = (float*)d_out;

    cudaFuncSetAttribute(gemm_in_kernel, cudaFuncAttributeMaxDynamicSharedMemorySize, GEMM_SMEM);
    cudaFuncSetAttribute(gemm_out_kernel, cudaFuncAttributeMaxDynamicSharedMemorySize, GEMM_SMEM);

    // 1) round x and in_proj_w to fp16
    {
        int n = BL * Dm;
        round_x_kernel<<<(n + 255) / 256, 256>>>(x, n);
        n = ProjD * Dm;
        round_w_kernel<<<(n + 255) / 256, 256>>>(in_proj_w, n);
    }
    // 2) in-projection GEMM (1-pass fp16)
    {
        dim3 grid((ProjD + 127) / 128, BL / 128);
        gemm_in_kernel<<<grid, 256, GEMM_SMEM>>>();
    }
    // 3) conv + SiLU
    {
        dim3 grid(ConvD / 256, Ll / 32, Bb);
        conv_silu_kernel<<<grid, 256>>>(conv_w, conv_b);
    }
    // 4) cumsum of dt*A (fused softplus)
    acum_kernel<<<Bb * Nc * Hh, Ck>>>(A_log, dt_bias);
    // 5) Gm = C B^T
    {
        dim3 grid(Bb * Nc, Ck / 64, Ck / 64);
        gm_kernel<<<grid, 256>>>();
    }
    // 6) states (fp16 mma)
    {
        dim3 grid(Bb * Nc, Hh);
        states_kernel<<<grid, 256>>>();
    }
    // 7) inter-chunk recurrence
    {
        int total = Bb * Hh * Pp * Nn;
        prev_kernel<<<(total + 255) / 256, 256>>>();
    }
    // 8) fused Y_diag + Y_off + D residual (tensor cores)
    {
        dim3 grid(Bb * Nc, Hh, Ck / 64);
        ydiag_yoff_kernel<<<grid, 256>>>(Dv);
    }
    // 9) gated RMSNorm (writes fp16 y)
    norm_kernel<<<BL, 256>>>(norm_w);
    // 10) round out_proj_w to fp16
    {
        int n = Dm * Inter;
        round_w_kernel<<<(n + 255) / 256, 256>>>(out_proj_w, n);
    }
    // 11) out-projection GEMM (1-pass fp16)
    {
        dim3 grid(Dm / 128, BL / 128);
        gemm_out_kernel<<<grid, 256, GEMM_SMEM>>>(out);
    }
    (void)in_sizes; (void)n_in; (void)out_size;
}

// round 16
// speedup vs baseline: 1.4931x; 1.4931x over previous
#include <cuda_runtime.h>
#include <cuda_fp16.h>
#include <math.h>
#include <stdint.h>

// ---------------------------------------------------------------------------
// Problem constants (fixed shapes)
// ---------------------------------------------------------------------------
#define Bb     2
#define Ll     2048
#define Dm     1024
#define Hh     32
#define Pp     64
#define Nn     128
#define KCONV  4
#define Ck     256
#define Nc     8          // Ll / Ck
#define Inter  2048
#define ConvD  2304
#define ProjD  4384
#define BL     (Bb * Ll)  // 4096

// ---------------------------------------------------------------------------
// Scratch (device globals; no dynamic allocation allowed)
// ---------------------------------------------------------------------------
__device__ float g_proj[(size_t)BL * ProjD];
__device__ float g_conv[(size_t)BL * ConvD];
__device__ float g_dtv[(size_t)BL * Hh];
__device__ float g_acum[(size_t)Bb * Nc * Hh * Ck];
__device__ float g_gm[(size_t)Bb * Nc * Ck * Ck];
__device__ float g_y[(size_t)BL * Inter];
__device__ float g_states[(size_t)Bb * Nc * Hh * Pp * Nn];
__device__ float g_prev[(size_t)Bb * Nc * Hh * Pp * Nn];

// fp16 buffers
__device__ __half g_Ah[(size_t)BL * Inter];
__device__ __half g_Bh[(size_t)ProjD * Dm];

__device__ __forceinline__ float siluf(float x) { return x / (1.f + expf(-x)); }

__device__ __forceinline__ float4 ldg4(const float* p) {
    return *reinterpret_cast<const float4*>(p);
}

// ---------------------------------------------------------------------------
// PTX helpers
// ---------------------------------------------------------------------------
__device__ __forceinline__ unsigned su32(const void* p) {
    return (unsigned)__cvta_generic_to_shared(p);
}

__device__ __forceinline__ void cp16(unsigned dst, const void* src, bool ok) {
    int sz = ok ? 16 : 0;
    asm volatile("cp.async.cg.shared.global [%0], [%1], 16, %2;\n"
                 :: "r"(dst), "l"(src), "r"(sz));
}

__device__ __forceinline__ void ldsm4(unsigned& r0, unsigned& r1, unsigned& r2, unsigned& r3,
                                      unsigned addr) {
    asm volatile("ldmatrix.sync.aligned.m8n8.x4.shared.b16 {%0,%1,%2,%3}, [%4];"
                 : "=r"(r0), "=r"(r1), "=r"(r2), "=r"(r3) : "r"(addr));
}

__device__ __forceinline__ void mma16816(float* c, const unsigned* a, const unsigned* b) {
    asm volatile(
        "mma.sync.aligned.m16n8k16.row.col.f32.f16.f16.f32 "
        "{%0,%1,%2,%3}, {%4,%5,%6,%7}, {%8,%9}, {%0,%1,%2,%3};"
        : "+f"(c[0]), "+f"(c[1]), "+f"(c[2]), "+f"(c[3])
        : "r"(a[0]), "r"(a[1]), "r"(a[2]), "r"(a[3]), "r"(b[0]), "r"(b[1]));
}

// ---------------------------------------------------------------------------
// Tensor-core fp16 GEMM, 1-pass: C = Ah*Bh, fp32 accum. (proven R10/R11)
// ---------------------------------------------------------------------------
#define GEMM_SMEM (2 * 36864)

struct Frags {
    unsigned ah[4][4];
    unsigned bh[4][2];
};

__device__ __forceinline__ void load_frags(Frags& F, unsigned stg, int ks,
                                           int wm, int wn, int lane) {
    const int rA = lane & 15;
    const int cB = ((lane >> 4) << 4);
    const unsigned colb = (unsigned)(ks * 32 + cB);
#pragma unroll
    for (int mf = 0; mf < 4; mf++) {
        unsigned ra = stg + (wm * 64 + mf * 16 + rA) * 144 + colb;
        ldsm4(F.ah[mf][0], F.ah[mf][1], F.ah[mf][2], F.ah[mf][3], ra);
    }
#pragma unroll
    for (int nf2 = 0; nf2 < 2; nf2++) {
        unsigned rb = stg + 18432 + (wn * 32 + nf2 * 16 + rA) * 144 + colb;
        unsigned t0, t1, t2, t3;
        ldsm4(t0, t1, t2, t3, rb);
        F.bh[nf2 * 2][0] = t0; F.bh[nf2 * 2][1] = t2;
        F.bh[nf2 * 2 + 1][0] = t1; F.bh[nf2 * 2 + 1][1] = t3;
    }
}

__device__ __forceinline__ void gemm_core(const __half* __restrict__ Ah,
                                          const __half* __restrict__ Bh,
                                          float* __restrict__ C,
                                          int M, int N, int K) {
    extern __shared__ char dyn[];
    const unsigned sbase = su32(dyn);
    const int tid = threadIdx.x;
    const int lane = tid & 31;
    const int warp = tid >> 5;
    const int wm = warp >> 2;
    const int wn = warp & 3;
    const int m0 = blockIdx.y * 128;
    const int n0 = blockIdx.x * 128;
    const int KB = K >> 6;

    float acc[4][4][4];
#pragma unroll
    for (int a = 0; a < 4; a++)
#pragma unroll
        for (int b = 0; b < 4; b++)
#pragma unroll
            for (int c = 0; c < 4; c++) acc[a][b][c] = 0.f;

    auto issue = [&](int kc, int st) {
        unsigned stg = sbase + st * 36864;
#pragma unroll
        for (int i = 0; i < 8; i++) {
            int q = tid + (i << 8);
            int mat = q >> 10;
            int r = (q >> 3) & 127;
            int c16 = q & 7;
            const __half* base = mat ? Bh : Ah;
            int gr = (mat ? n0 : m0) + r;
            bool ok = gr < (mat ? N : M);
            if (!ok) gr = (mat ? N : M) - 1;
            const void* src = base + (size_t)gr * K + (kc << 6) + (c16 << 3);
            unsigned dst = stg + mat * 18432 + r * 144 + (c16 << 4);
            cp16(dst, src, ok);
        }
        asm volatile("cp.async.commit_group;\n");
    };

    issue(0, 0);
    if (KB > 1) issue(1, 1);

    Frags F[2];

    for (int kb = 0; kb < KB; kb++) {
        int st = kb & 1;
        if (kb + 1 < KB) asm volatile("cp.async.wait_group 1;\n");
        else             asm volatile("cp.async.wait_group 0;\n");
        __syncthreads();
        unsigned stg = sbase + st * 36864;

        load_frags(F[0], stg, 0, wm, wn, lane);
#pragma unroll
        for (int ks = 0; ks < 4; ks++) {
            if (ks < 3) load_frags(F[(ks + 1) & 1], stg, ks + 1, wm, wn, lane);
            Frags& f = F[ks & 1];
#pragma unroll
            for (int mf = 0; mf < 4; mf++)
#pragma unroll
                for (int nf = 0; nf < 4; nf++)
                    mma16816(acc[mf][nf], f.ah[mf], f.bh[nf]);
        }
        __syncthreads();
        if (kb + 2 < KB) issue(kb + 2, st);
    }

    int g4 = lane >> 2, t4 = lane & 3;
#pragma unroll
    for (int mf = 0; mf < 4; mf++) {
        int r0 = m0 + wm * 64 + mf * 16 + g4;
#pragma unroll
        for (int nf = 0; nf < 4; nf++) {
            int cg = n0 + wn * 32 + nf * 8 + t4 * 2;
            if (cg < N) {
                float* p0 = C + (size_t)r0 * N + cg;
                p0[0] = acc[mf][nf][0];
                p0[1] = acc[mf][nf][1];
                float* p1 = p0 + (size_t)8 * N;
                p1[0] = acc[mf][nf][2];
                p1[1] = acc[mf][nf][3];
            }
        }
    }
}

__global__ __launch_bounds__(256) void gemm_in_kernel() {
    gemm_core(g_Ah, g_Bh, g_proj, BL, ProjD, Dm);
}

__global__ __launch_bounds__(256) void gemm_out_kernel(float* __restrict__ out) {
    gemm_core(g_Ah, g_Bh, out, BL, Dm, Inter);
}

// ---------------------------------------------------------------------------
// fp16 conversions
// ---------------------------------------------------------------------------
__global__ void round_x_kernel(const float* __restrict__ in, int n) {
    int i = blockIdx.x * blockDim.x + threadIdx.x;
    if (i >= n) return;
    g_Ah[i] = __float2half(in[i]);
}

__global__ void round_w_kernel(const float* __restrict__ in, int n) {
    int i = blockIdx.x * blockDim.x + threadIdx.x;
    if (i >= n) return;
    g_Bh[i] = __float2half(in[i]);
}

// ---------------------------------------------------------------------------
// Depthwise causal conv1d + SiLU (sliding window, 32 positions/thread)
// ---------------------------------------------------------------------------
__global__ __launch_bounds__(256) void conv_silu_kernel(const float* __restrict__ cw,
                                                        const float* __restrict__ cb) {
    int ch = blockIdx.x * 256 + threadIdx.x;
    int l0 = blockIdx.y * 32;
    int b  = blockIdx.z;
    const float* col = g_proj + (size_t)b * Ll * ProjD + Inter + ch;
    float w0 = cw[ch * KCONV + 0];
    float w1 = cw[ch * KCONV + 1];
    float w2 = cw[ch * KCONV + 2];
    float w3 = cw[ch * KCONV + 3];
    float bias = cb[ch];
    float xm3 = (l0 >= 3) ? col[(size_t)(l0 - 3) * ProjD] : 0.f;
    float xm2 = (l0 >= 2) ? col[(size_t)(l0 - 2) * ProjD] : 0.f;
    float xm1 = (l0 >= 1) ? col[(size_t)(l0 - 1) * ProjD] : 0.f;
    float* outp = g_conv + (size_t)(b * Ll + l0) * ConvD + ch;
#pragma unroll 4
    for (int i = 0; i < 32; i++) {
        float x0 = col[(size_t)(l0 + i) * ProjD];
        float acc = bias + w0 * xm3 + w1 * xm2 + w2 * xm1 + w3 * x0;
        outp[(size_t)i * ConvD] = siluf(acc);
        xm3 = xm2; xm2 = xm1; xm1 = x0;
    }
}

// ---------------------------------------------------------------------------
// Per-chunk inclusive cumsum of dt * A with fused softplus
// ---------------------------------------------------------------------------
__global__ void acum_kernel(const float* __restrict__ A_log,
                            const float* __restrict__ dt_bias) {
    int blk = blockIdx.x;
    int h = blk % Hh;
    int bc = blk / Hh;
    int b = bc / Nc, c = bc % Nc;
    int t = threadIdx.x;
    float A = -expf(A_log[h]);
    int bl = b * Ll + c * Ck + t;
    float raw = g_proj[(size_t)bl * ProjD + Inter + ConvD + h] + dt_bias[h];
    float dt = (raw > 20.f) ? raw : log1pf(expf(raw));
    g_dtv[(size_t)bl * Hh + h] = dt;
    float v = dt * A;
    __shared__ float s[Ck];
    s[t] = v;
    __syncthreads();
    for (int off = 1; off < Ck; off <<= 1) {
        float x = (t >= off) ? s[t - off] : 0.f;
        __syncthreads();
        s[t] += x;
        __syncthreads();
    }
    g_acum[(size_t)blk * Ck + t] = s[t];
}

// ---------------------------------------------------------------------------
// Gm[s,z] = sum_n C[s,n] * B[z,n] per (b,c), lower triangle (fp32, R11)
// ---------------------------------------------------------------------------
__global__ __launch_bounds__(256) void gm_kernel() {
    int bc = blockIdx.x;
    int sT = blockIdx.y, zT = blockIdx.z;
    if (zT > sT) return;
    int b = bc / Nc, c = bc % Nc;
    int rowbase = b * Ll + c * Ck;
    __shared__ __align__(16) float Cs[16][68];
    __shared__ __align__(16) float Bs[16][68];
    int tid = threadIdx.x;
    int ty = tid >> 4, tx = tid & 15;
    float acc[4][4];
#pragma unroll
    for (int i = 0; i < 4; i++)
#pragma unroll
        for (int j = 0; j < 4; j++) acc[i][j] = 0.f;

    int lrow = tid >> 2;
    int lcol = (tid & 3) * 4;

    for (int n0 = 0; n0 < Nn; n0 += 16) {
        float4 vc = ldg4(g_conv + (size_t)(rowbase + sT * 64 + lrow) * ConvD + Inter + Nn + n0 + lcol);
        float4 vb = ldg4(g_conv + (size_t)(rowbase + zT * 64 + lrow) * ConvD + Inter + n0 + lcol);
        Cs[lcol + 0][lrow] = vc.x; Cs[lcol + 1][lrow] = vc.y;
        Cs[lcol + 2][lrow] = vc.z; Cs[lcol + 3][lrow] = vc.w;
        Bs[lcol + 0][lrow] = vb.x; Bs[lcol + 1][lrow] = vb.y;
        Bs[lcol + 2][lrow] = vb.z; Bs[lcol + 3][lrow] = vb.w;
        __syncthreads();
#pragma unroll
        for (int kk = 0; kk < 16; kk++) {
            float4 rc = *(const float4*)&Cs[kk][ty * 4];
            float4 rb = *(const float4*)&Bs[kk][tx * 4];
            float rcv[4] = {rc.x, rc.y, rc.z, rc.w};
            float rbv[4] = {rb.x, rb.y, rb.z, rb.w};
#pragma unroll
            for (int i = 0; i < 4; i++)
#pragma unroll
                for (int j = 0; j < 4; j++) acc[i][j] += rcv[i] * rbv[j];
        }
        __syncthreads();
    }
#pragma unroll
    for (int i = 0; i < 4; i++) {
        int sg = sT * 64 + ty * 4 + i;
        float* pg = g_gm + ((size_t)bc * Ck + sg) * Ck + zT * 64 + tx * 4;
        *reinterpret_cast<float4*>(pg) = make_float4(acc[i][0], acc[i][1], acc[i][2], acc[i][3]);
    }
}

// ---------------------------------------------------------------------------
// states — fp16 mma: out[p=64][n=128] = sum_l H[p,l]*B[n,l], K=256 in 4 chunks.
// 8 warps = 4(m p-tiles of 16) x 2(n halves of 64). Coalesced float2 epilogue.
// ---------------------------------------------------------------------------
__global__ __launch_bounds__(256) void states_kernel() {
    int bc = blockIdx.x, h = blockIdx.y;
    int b = bc / Nc, c = bc % Nc;
    int tid = threadIdx.x;
    int lane = tid & 31;
    int warp = tid >> 5;
    int wm = warp >> 1;   // 0..3
    int wn = warp & 1;    // 0..1

    __shared__ __align__(16) __half Hsh[64][72];    // [p][l]
    __shared__ __align__(16) __half Bsh[128][72];   // [n][l]

    const float* acumC = g_acum + ((size_t)bc * Hh + h) * Ck;
    float aLast = acumC[Ck - 1];
    int rowbase = b * Ll + c * Ck;

    float acc[8][4];
#pragma unroll
    for (int i = 0; i < 8; i++)
#pragma unroll
        for (int j = 0; j < 4; j++) acc[i][j] = 0.f;

    const unsigned hbv = su32(Hsh);
    const unsigned bbv = su32(Bsh);
    const int rA = lane & 15;
    const int cBy = (lane >> 4) << 4;

    for (int lc = 0; lc < 4; lc++) {
        {
            // Hsh[p][l] = hs[l][p] * dt[l] * exp(aLast - acum[l]) (transposed)
            int ll = tid >> 2;
            int p0 = (tid & 3) * 16;
            int l = rowbase + lc * 64 + ll;
            float w = g_dtv[(size_t)l * Hh + h] * expf(aLast - acumC[lc * 64 + ll]);
            const float* ph = g_conv + (size_t)l * ConvD + h * Pp + p0;
#pragma unroll
            for (int u = 0; u < 4; u++) {
                float4 v = ldg4(ph + u * 4);
                Hsh[p0 + u * 4 + 0][ll] = __float2half(v.x * w);
                Hsh[p0 + u * 4 + 1][ll] = __float2half(v.y * w);
                Hsh[p0 + u * 4 + 2][ll] = __float2half(v.z * w);
                Hsh[p0 + u * 4 + 3][ll] = __float2half(v.w * w);
            }
        }
#pragma unroll
        for (int i = 0; i < 8; i++) {
            // Bsh[n][l] = B[l][n] (transposed)
            int q = tid + (i << 8);
            int ll = q >> 5;
            int n4 = (q & 31) * 4;
            float4 v = ldg4(g_conv + (size_t)(rowbase + lc * 64 + ll) * ConvD + Inter + n4);
            Bsh[n4 + 0][ll] = __float2half(v.x);
            Bsh[n4 + 1][ll] = __float2half(v.y);
            Bsh[n4 + 2][ll] = __float2half(v.z);
            Bsh[n4 + 3][ll] = __float2half(v.w);
        }
        __syncthreads();
#pragma unroll
        for (int ks = 0; ks < 4; ks++) {
            unsigned colb = (unsigned)(ks * 32 + cBy);
            unsigned a[4];
            ldsm4(a[0], a[1], a[2], a[3], hbv + (wm * 16 + rA) * 144 + colb);
            unsigned bfr[8][2];
#pragma unroll
            for (int nf2 = 0; nf2 < 4; nf2++) {
                unsigned rb = bbv + (wn * 64 + nf2 * 16 + rA) * 144 + colb;
                unsigned t0, t1, t2, t3;
                ldsm4(t0, t1, t2, t3, rb);
                bfr[nf2 * 2][0] = t0; bfr[nf2 * 2][1] = t2;
                bfr[nf2 * 2 + 1][0] = t1; bfr[nf2 * 2 + 1][1] = t3;
            }
#pragma unroll
            for (int nf = 0; nf < 8; nf++)
                mma16816(acc[nf], a, bfr[nf]);
        }
        __syncthreads();
    }

    float* ps = g_states + ((size_t)bc * Hh + h) * Pp * Nn;
    int g4 = lane >> 2, t4 = lane & 3;
    int p0r = wm * 16 + g4;
#pragma unroll
    for (int nf = 0; nf < 8; nf++) {
        int n = wn * 64 + nf * 8 + t4 * 2;
        *(float2*)(ps + (size_t)p0r * Nn + n) = make_float2(acc[nf][0], acc[nf][1]);
        *(float2*)(ps + (size_t)(p0r + 8) * Nn + n) = make_float2(acc[nf][2], acc[nf][3]);
    }
}

// ---------------------------------------------------------------------------
// Inter-chunk recurrence
// ---------------------------------------------------------------------------
__global__ void prev_kernel() {
    int idx = blockIdx.x * blockDim.x + threadIdx.x;
    if (idx >= Bb * Hh * Pp * Nn) return;
    int n = idx % Nn;
    int p = (idx / Nn) % Pp;
    int h = (idx / (Nn * Pp)) % Hh;
    int b = idx / (Nn * Pp * Hh);
    float r = 0.f;
    for (int c = 0; c < Nc; c++) {
        size_t off = (((size_t)(b * Nc + c) * Hh + h) * Pp + p) * Nn + n;
        g_prev[off] = r;
        float zl = g_acum[((size_t)(b * Nc + c) * Hh + h) * Ck + (Ck - 1)];
        r = g_states[off] + expf(zl) * r;
    }
}

// ---------------------------------------------------------------------------
// FUSED Y_diag + Y_off + D residual — tensor-core version (R14, proven).
// ---------------------------------------------------------------------------
__global__ __launch_bounds__(256) void ydiag_yoff_kernel(const float* __restrict__ Dv) {
    int bc = blockIdx.x;
    int h = blockIdx.y;
    int sT = blockIdx.z;
    int b = bc / Nc, c = bc % Nc;
    int tid = threadIdx.x;
    int lane = tid & 31;
    int warp = tid >> 5;
    int wm = warp >> 1;     // 0..3 (16 rows each)
    int wn = warp & 1;      // 0..1 (32 cols each)

    __shared__ __align__(16) char sb[34816];
    __half* Msh = (__half*)sb;            // [64][72]  A: [s][z]
    __half* Hsh = (__half*)(sb + 9216);   // [64][72]  B: [p][z]
    __half* Csh = (__half*)sb;            // [64][136] A: [l][n]
    __half* Psh = (__half*)(sb + 17408);  // [64][136] B: [p][n]
    __shared__ float sAc[64], zAc[64], ezs[64];

    const float* acumC = g_acum + ((size_t)bc * Hh + h) * Ck;
    if (tid < 64) sAc[tid] = acumC[sT * 64 + tid];
    int rowbase = b * Ll + c * Ck;
    int lbase = rowbase + sT * 64;

    const unsigned mbase = su32(Msh);
    const unsigned hbase = su32(Hsh);
    const int rA = lane & 15;
    const int cBy = (lane >> 4) << 4;

    float accd[4][4];
#pragma unroll
    for (int i = 0; i < 4; i++)
#pragma unroll
        for (int j = 0; j < 4; j++) accd[i][j] = 0.f;

    for (int zT = 0; zT <= sT; zT++) {
        float M = acumC[zT * 64 + 63];
        if (tid < 64) {
            float az = acumC[zT * 64 + tid];
            zAc[tid] = az;
            ezs[tid] = expf(M - az);
        }
        {
            int zz = tid >> 2;
            int p0 = (tid & 3) * 16;
            int l = rowbase + zT * 64 + zz;
            float d = g_dtv[(size_t)l * Hh + h];
            const float* ph = g_conv + (size_t)l * ConvD + h * Pp + p0;
#pragma unroll
            for (int u = 0; u < 4; u++) {
                float4 v = ldg4(ph + u * 4);
                Hsh[(p0 + u * 4 + 0) * 72 + zz] = __float2half(v.x * d);
                Hsh[(p0 + u * 4 + 1) * 72 + zz] = __float2half(v.y * d);
                Hsh[(p0 + u * 4 + 2) * 72 + zz] = __float2half(v.z * d);
                Hsh[(p0 + u * 4 + 3) * 72 + zz] = __float2half(v.w * d);
            }
        }
        __syncthreads();
        {
            int zz4 = (tid & 15) * 4;
            int ss4 = (tid >> 4) * 4;
            if (zT < sT) {
#pragma unroll
                for (int a = 0; a < 4; a++) {
                    int ss = ss4 + a;
                    int sg = sT * 64 + ss;
                    float es = expf(sAc[ss] - M);
                    float4 g = ldg4(g_gm + ((size_t)bc * Ck + sg) * Ck + zT * 64 + zz4);
                    float m0 = g.x * ezs[zz4 + 0] * es;
                    float m1 = g.y * ezs[zz4 + 1] * es;
                    float m2 = g.z * ezs[zz4 + 2] * es;
                    float m3 = g.w * ezs[zz4 + 3] * es;
                    *(half2*)&Msh[ss * 72 + zz4]     = __floats2half2_rn(m0, m1);
                    *(half2*)&Msh[ss * 72 + zz4 + 2] = __floats2half2_rn(m2, m3);
                }
            } else {
#pragma unroll
                for (int a = 0; a < 4; a++) {
                    int ss = ss4 + a;
                    int sg = sT * 64 + ss;
                    float as = sAc[ss];
                    float4 g = ldg4(g_gm + ((size_t)bc * Ck + sg) * Ck + zT * 64 + zz4);
                    float gv[4] = {g.x, g.y, g.z, g.w};
                    float mv[4];
#pragma unroll
                    for (int q = 0; q < 4; q++) {
                        int zz = zz4 + q;
                        mv[q] = ((zT * 64 + zz) <= sg) ? gv[q] * expf(as - zAc[zz]) : 0.f;
                    }
                    *(half2*)&Msh[ss * 72 + zz4]     = __floats2half2_rn(mv[0], mv[1]);
                    *(half2*)&Msh[ss * 72 + zz4 + 2] = __floats2half2_rn(mv[2], mv[3]);
                }
            }
        }
        __syncthreads();
#pragma unroll
        for (int ks = 0; ks < 4; ks++) {
            unsigned colb = (unsigned)(ks * 32 + cBy);
            unsigned a[4];
            ldsm4(a[0], a[1], a[2], a[3], mbase + (wm * 16 + rA) * 144 + colb);
            unsigned bh[4][2];
#pragma unroll
            for (int nf2 = 0; nf2 < 2; nf2++) {
                unsigned rb = hbase + (wn * 32 + nf2 * 16 + rA) * 144 + colb;
                unsigned t0, t1, t2, t3;
                ldsm4(t0, t1, t2, t3, rb);
                bh[nf2 * 2][0] = t0; bh[nf2 * 2][1] = t2;
                bh[nf2 * 2 + 1][0] = t1; bh[nf2 * 2 + 1][1] = t3;
            }
#pragma unroll
            for (int nf = 0; nf < 4; nf++)
                mma16816(accd[nf], a, bh[nf]);
        }
        __syncthreads();
    }

    float acco[4][4];
#pragma unroll
    for (int i = 0; i < 4; i++)
#pragma unroll
        for (int j = 0; j < 4; j++) acco[i][j] = 0.f;

    const float* pprev = g_prev + ((size_t)bc * Hh + h) * Pp * Nn;
#pragma unroll
    for (int i = 0; i < 8; i++) {
        int q = tid + (i << 8);
        int row = q >> 5;
        int c4 = (q & 31) * 4;
        float4 vc = ldg4(g_conv + (size_t)(lbase + row) * ConvD + Inter + Nn + c4);
        *(half2*)&Csh[row * 136 + c4]     = __floats2half2_rn(vc.x, vc.y);
        *(half2*)&Csh[row * 136 + c4 + 2] = __floats2half2_rn(vc.z, vc.w);
        float4 vp = ldg4(pprev + (size_t)row * Nn + c4);
        *(half2*)&Psh[row * 136 + c4]     = __floats2half2_rn(vp.x, vp.y);
        *(half2*)&Psh[row * 136 + c4 + 2] = __floats2half2_rn(vp.z, vp.w);
    }
    __syncthreads();
    const unsigned cbase2 = su32(Csh);
    const unsigned pbase2 = su32(Psh);
#pragma unroll
    for (int ks = 0; ks < 8; ks++) {
        unsigned colb = (unsigned)(ks * 32 + cBy);
        unsigned a[4];
        ldsm4(a[0], a[1], a[2], a[3], cbase2 + (wm * 16 + rA) * 272 + colb);
        unsigned bh[4][2];
#pragma unroll
        for (int nf2 = 0; nf2 < 2; nf2++) {
            unsigned rb = pbase2 + (wn * 32 + nf2 * 16 + rA) * 272 + colb;
            unsigned t0, t1, t2, t3;
            ldsm4(t0, t1, t2, t3, rb);
            bh[nf2 * 2][0] = t0; bh[nf2 * 2][1] = t2;
            bh[nf2 * 2 + 1][0] = t1; bh[nf2 * 2 + 1][1] = t3;
        }
#pragma unroll
        for (int nf = 0; nf < 4; nf++)
            mma16816(acco[nf], a, bh[nf]);
    }

    float Dh = Dv[h];
    int r0 = wm * 16 + (lane >> 2);
    int pb0 = wn * 32 + (lane & 3) * 2;
    float sd0 = expf(sAc[r0]);
    float sd1 = expf(sAc[r0 + 8]);
    int l0v = lbase + r0;
    int l1v = l0v + 8;
#pragma unroll
    for (int nf = 0; nf < 4; nf++) {
        int p = pb0 + nf * 8;
        float2 hv0 = *(const float2*)(g_conv + (size_t)l0v * ConvD + h * Pp + p);
        float2 o0;
        o0.x = accd[nf][0] + acco[nf][0] * sd0 + Dh * hv0.x;
        o0.y = accd[nf][1] + acco[nf][1] * sd0 + Dh * hv0.y;
        *(float2*)(g_y + (size_t)l0v * Inter + h * Pp + p) = o0;
        float2 hv1 = *(const float2*)(g_conv + (size_t)l1v * ConvD + h * Pp + p);
        float2 o1;
        o1.x = accd[nf][2] + acco[nf][2] * sd1 + Dh * hv1.x;
        o1.y = accd[nf][3] + acco[nf][3] * sd1 + Dh * hv1.y;
        *(float2*)(g_y + (size_t)l1v * Inter + h * Pp + p) = o1;
    }
}

// ---------------------------------------------------------------------------
// Gated RMSNorm; writes fp16-rounded y for the 1-pass out-proj
// ---------------------------------------------------------------------------
__global__ __launch_bounds__(256) void norm_kernel(const float* __restrict__ norm_w) {
    int row = blockIdx.x;
    int tid = threadIdx.x;
    const float* pg = g_proj + (size_t)row * ProjD;
    const float* py = g_y + (size_t)row * Inter;
    float f[8];
    float ss = 0.f;
#pragma unroll
    for (int u = 0; u < 8; u++) {
        int i = tid + u * 256;
        float g = pg[i];
        float v = py[i] * siluf(g);
        f[u] = v;
        ss += v * v;
    }
    __shared__ float red[8];
    int lane = tid & 31, wid = tid >> 5;
#pragma unroll
    for (int o = 16; o > 0; o >>= 1) ss += __shfl_xor_sync(0xffffffffu, ss, o);
    if (lane == 0) red[wid] = ss;
    __syncthreads();
    if (tid == 0) {
        float t = 0.f;
#pragma unroll
        for (int i = 0; i < 8; i++) t += red[i];
        red[0] = t;
    }
    __syncthreads();
    float rs = rsqrtf(red[0] / (float)Inter + 1e-6f);
#pragma unroll
    for (int u = 0; u < 8; u++) {
        int i = tid + u * 256;
        float v = f[u] * rs * norm_w[i];
        g_Ah[(size_t)row * Inter + i] = __float2half(v);
    }
}

// ---------------------------------------------------------------------------
// Launch
// ---------------------------------------------------------------------------
extern "C" void kernel_launch(void* const* d_in, const int* in_sizes, int n_in,
                              void* d_out, int out_size) {
    const float* x         = (const float*)d_in[0];
    const float* in_proj_w = (const float*)d_in[1];
    const float* conv_w    = (const float*)d_in[2];
    const float* conv_b    = (const float*)d_in[3];
    const float* dt_bias   = (const float*)d_in[4];
    const float* A_log     = (const float*)d_in[5];
    const float* Dv        = (const float*)d_in[6];
    const float* norm_w    = (const float*)d_in[7];
    const float* out_proj_w= (const float*)d_in[8];
    float* out = (float*)d_out;

    cudaFuncSetAttribute(gemm_in_kernel, cudaFuncAttributeMaxDynamicSharedMemorySize, GEMM_SMEM);
    cudaFuncSetAttribute(gemm_out_kernel, cudaFuncAttributeMaxDynamicSharedMemorySize, GEMM_SMEM);

    // 1) round x and in_proj_w to fp16
    {
        int n = BL * Dm;
        round_x_kernel<<<(n + 255) / 256, 256>>>(x, n);
        n = ProjD * Dm;
        round_w_kernel<<<(n + 255) / 256, 256>>>(in_proj_w, n);
    }
    // 2) in-projection GEMM (1-pass fp16)
    {
        dim3 grid((ProjD + 127) / 128, BL / 128);
        gemm_in_kernel<<<grid, 256, GEMM_SMEM>>>();
    }
    // 3) conv + SiLU
    {
        dim3 grid(ConvD / 256, Ll / 32, Bb);
        conv_silu_kernel<<<grid, 256>>>(conv_w, conv_b);
    }
    // 4) cumsum of dt*A (fused softplus)
    acum_kernel<<<Bb * Nc * Hh, Ck>>>(A_log, dt_bias);
    // 5) Gm = C B^T
    {
        dim3 grid(Bb * Nc, Ck / 64, Ck / 64);
        gm_kernel<<<grid, 256>>>();
    }
    // 6) states (fp16 mma)
    {
        dim3 grid(Bb * Nc, Hh);
        states_kernel<<<grid, 256>>>();
    }
    // 7) inter-chunk recurrence
    {
        int total = Bb * Hh * Pp * Nn;
        prev_kernel<<<(total + 255) / 256, 256>>>();
    }
    // 8) fused Y_diag + Y_off + D residual (tensor cores)
    {
        dim3 grid(Bb * Nc, Hh, Ck / 64);
        ydiag_yoff_kernel<<<grid, 256>>>(Dv);
    }
    // 9) gated RMSNorm (writes fp16 y)
    norm_kernel<<<BL, 256>>>(norm_w);
    // 10) round out_proj_w to fp16
    {
        int n = Dm * Inter;
        round_w_kernel<<<(n + 255) / 256, 256>>>(out_proj_w, n);
    }
    // 11) out-projection GEMM (1-pass fp16)
    {
        dim3 grid(Dm / 128, BL / 128);
        gemm_out_kernel<<<grid, 256, GEMM_SMEM>>>(out);
    }
    (void)in_sizes; (void)n_in; (void)out_size;
}

// round 17
// speedup vs baseline: 1.5152x; 1.0148x over previous
#include <cuda_runtime.h>
#include <cuda_fp16.h>
#include <math.h>
#include <stdint.h>

// ---------------------------------------------------------------------------
// Problem constants (fixed shapes)
// ---------------------------------------------------------------------------
#define Bb     2
#define Ll     2048
#define Dm     1024
#define Hh     32
#define Pp     64
#define Nn     128
#define KCONV  4
#define Ck     256
#define Nc     8          // Ll / Ck
#define Inter  2048
#define ConvD  2304
#define ProjD  4384
#define BL     (Bb * Ll)  // 4096

// ---------------------------------------------------------------------------
// Scratch (device globals; no dynamic allocation allowed)
// ---------------------------------------------------------------------------
__device__ float g_proj[(size_t)BL * ProjD];
__device__ __half g_convh[(size_t)BL * ConvD];      // conv output, fp16
__device__ float g_dtv[(size_t)BL * Hh];
__device__ float g_acum[(size_t)Bb * Nc * Hh * Ck];
__device__ float g_gm[(size_t)Bb * Nc * Ck * Ck];
__device__ float g_y[(size_t)BL * Inter];
__device__ float g_states[(size_t)Bb * Nc * Hh * Pp * Nn];
__device__ float g_prev[(size_t)Bb * Nc * Hh * Pp * Nn];

// fp16 buffers
__device__ __half g_Ah[(size_t)BL * Inter];
__device__ __half g_Bh[(size_t)ProjD * Dm];

__device__ __forceinline__ float siluf(float x) { return x / (1.f + expf(-x)); }

__device__ __forceinline__ float4 ldg4(const float* p) {
    return *reinterpret_cast<const float4*>(p);
}

// ---------------------------------------------------------------------------
// PTX helpers
// ---------------------------------------------------------------------------
__device__ __forceinline__ unsigned su32(const void* p) {
    return (unsigned)__cvta_generic_to_shared(p);
}

__device__ __forceinline__ void cp16(unsigned dst, const void* src, bool ok) {
    int sz = ok ? 16 : 0;
    asm volatile("cp.async.cg.shared.global [%0], [%1], 16, %2;\n"
                 :: "r"(dst), "l"(src), "r"(sz));
}

__device__ __forceinline__ void ldsm4(unsigned& r0, unsigned& r1, unsigned& r2, unsigned& r3,
                                      unsigned addr) {
    asm volatile("ldmatrix.sync.aligned.m8n8.x4.shared.b16 {%0,%1,%2,%3}, [%4];"
                 : "=r"(r0), "=r"(r1), "=r"(r2), "=r"(r3) : "r"(addr));
}

__device__ __forceinline__ void mma16816(float* c, const unsigned* a, const unsigned* b) {
    asm volatile(
        "mma.sync.aligned.m16n8k16.row.col.f32.f16.f16.f32 "
        "{%0,%1,%2,%3}, {%4,%5,%6,%7}, {%8,%9}, {%0,%1,%2,%3};"
        : "+f"(c[0]), "+f"(c[1]), "+f"(c[2]), "+f"(c[3])
        : "r"(a[0]), "r"(a[1]), "r"(a[2]), "r"(a[3]), "r"(b[0]), "r"(b[1]));
}

// ---------------------------------------------------------------------------
// Tensor-core fp16 GEMM, 1-pass: C = Ah*Bh, fp32 accum. (proven R10/R11)
// ---------------------------------------------------------------------------
#define GEMM_SMEM (2 * 36864)

struct Frags {
    unsigned ah[4][4];
    unsigned bh[4][2];
};

__device__ __forceinline__ void load_frags(Frags& F, unsigned stg, int ks,
                                           int wm, int wn, int lane) {
    const int rA = lane & 15;
    const int cB = ((lane >> 4) << 4);
    const unsigned colb = (unsigned)(ks * 32 + cB);
#pragma unroll
    for (int mf = 0; mf < 4; mf++) {
        unsigned ra = stg + (wm * 64 + mf * 16 + rA) * 144 + colb;
        ldsm4(F.ah[mf][0], F.ah[mf][1], F.ah[mf][2], F.ah[mf][3], ra);
    }
#pragma unroll
    for (int nf2 = 0; nf2 < 2; nf2++) {
        unsigned rb = stg + 18432 + (wn * 32 + nf2 * 16 + rA) * 144 + colb;
        unsigned t0, t1, t2, t3;
        ldsm4(t0, t1, t2, t3, rb);
        F.bh[nf2 * 2][0] = t0; F.bh[nf2 * 2][1] = t2;
        F.bh[nf2 * 2 + 1][0] = t1; F.bh[nf2 * 2 + 1][1] = t3;
    }
}

__device__ __forceinline__ void gemm_core(const __half* __restrict__ Ah,
                                          const __half* __restrict__ Bh,
                                          float* __restrict__ C,
                                          int M, int N, int K) {
    extern __shared__ char dyn[];
    const unsigned sbase = su32(dyn);
    const int tid = threadIdx.x;
    const int lane = tid & 31;
    const int warp = tid >> 5;
    const int wm = warp >> 2;
    const int wn = warp & 3;
    const int m0 = blockIdx.y * 128;
    const int n0 = blockIdx.x * 128;
    const int KB = K >> 6;

    float acc[4][4][4];
#pragma unroll
    for (int a = 0; a < 4; a++)
#pragma unroll
        for (int b = 0; b < 4; b++)
#pragma unroll
            for (int c = 0; c < 4; c++) acc[a][b][c] = 0.f;

    auto issue = [&](int kc, int st) {
        unsigned stg = sbase + st * 36864;
#pragma unroll
        for (int i = 0; i < 8; i++) {
            int q = tid + (i << 8);
            int mat = q >> 10;
            int r = (q >> 3) & 127;
            int c16 = q & 7;
            const __half* base = mat ? Bh : Ah;
            int gr = (mat ? n0 : m0) + r;
            bool ok = gr < (mat ? N : M);
            if (!ok) gr = (mat ? N : M) - 1;
            const void* src = base + (size_t)gr * K + (kc << 6) + (c16 << 3);
            unsigned dst = stg + mat * 18432 + r * 144 + (c16 << 4);
            cp16(dst, src, ok);
        }
        asm volatile("cp.async.commit_group;\n");
    };

    issue(0, 0);
    if (KB > 1) issue(1, 1);

    Frags F[2];

    for (int kb = 0; kb < KB; kb++) {
        int st = kb & 1;
        if (kb + 1 < KB) asm volatile("cp.async.wait_group 1;\n");
        else             asm volatile("cp.async.wait_group 0;\n");
        __syncthreads();
        unsigned stg = sbase + st * 36864;

        load_frags(F[0], stg, 0, wm, wn, lane);
#pragma unroll
        for (int ks = 0; ks < 4; ks++) {
            if (ks < 3) load_frags(F[(ks + 1) & 1], stg, ks + 1, wm, wn, lane);
            Frags& f = F[ks & 1];
#pragma unroll
            for (int mf = 0; mf < 4; mf++)
#pragma unroll
                for (int nf = 0; nf < 4; nf++)
                    mma16816(acc[mf][nf], f.ah[mf], f.bh[nf]);
        }
        __syncthreads();
        if (kb + 2 < KB) issue(kb + 2, st);
    }

    int g4 = lane >> 2, t4 = lane & 3;
#pragma unroll
    for (int mf = 0; mf < 4; mf++) {
        int r0 = m0 + wm * 64 + mf * 16 + g4;
#pragma unroll
        for (int nf = 0; nf < 4; nf++) {
            int cg = n0 + wn * 32 + nf * 8 + t4 * 2;
            if (cg < N) {
                float* p0 = C + (size_t)r0 * N + cg;
                p0[0] = acc[mf][nf][0];
                p0[1] = acc[mf][nf][1];
                float* p1 = p0 + (size_t)8 * N;
                p1[0] = acc[mf][nf][2];
                p1[1] = acc[mf][nf][3];
            }
        }
    }
}

__global__ __launch_bounds__(256) void gemm_in_kernel() {
    gemm_core(g_Ah, g_Bh, g_proj, BL, ProjD, Dm);
}

__global__ __launch_bounds__(256) void gemm_out_kernel(float* __restrict__ out) {
    gemm_core(g_Ah, g_Bh, out, BL, Dm, Inter);
}

// ---------------------------------------------------------------------------
// fp16 conversions
// ---------------------------------------------------------------------------
__global__ void round_x_kernel(const float* __restrict__ in, int n) {
    int i = blockIdx.x * blockDim.x + threadIdx.x;
    if (i >= n) return;
    g_Ah[i] = __float2half(in[i]);
}

__global__ void round_w_kernel(const float* __restrict__ in, int n) {
    int i = blockIdx.x * blockDim.x + threadIdx.x;
    if (i >= n) return;
    g_Bh[i] = __float2half(in[i]);
}

// ---------------------------------------------------------------------------
// Depthwise causal conv1d + SiLU (sliding window); writes fp16 g_convh
// ---------------------------------------------------------------------------
__global__ __launch_bounds__(256) void conv_silu_kernel(const float* __restrict__ cw,
                                                        const float* __restrict__ cb) {
    int ch = blockIdx.x * 256 + threadIdx.x;
    int l0 = blockIdx.y * 32;
    int b  = blockIdx.z;
    const float* col = g_proj + (size_t)b * Ll * ProjD + Inter + ch;
    float w0 = cw[ch * KCONV + 0];
    float w1 = cw[ch * KCONV + 1];
    float w2 = cw[ch * KCONV + 2];
    float w3 = cw[ch * KCONV + 3];
    float bias = cb[ch];
    float xm3 = (l0 >= 3) ? col[(size_t)(l0 - 3) * ProjD] : 0.f;
    float xm2 = (l0 >= 2) ? col[(size_t)(l0 - 2) * ProjD] : 0.f;
    float xm1 = (l0 >= 1) ? col[(size_t)(l0 - 1) * ProjD] : 0.f;
    __half* outp = g_convh + (size_t)(b * Ll + l0) * ConvD + ch;
#pragma unroll 4
    for (int i = 0; i < 32; i++) {
        float x0 = col[(size_t)(l0 + i) * ProjD];
        float acc = bias + w0 * xm3 + w1 * xm2 + w2 * xm1 + w3 * x0;
        outp[(size_t)i * ConvD] = __float2half(siluf(acc));
        xm3 = xm2; xm2 = xm1; xm1 = x0;
    }
}

// ---------------------------------------------------------------------------
// Per-chunk inclusive cumsum of dt * A with fused softplus
// ---------------------------------------------------------------------------
__global__ void acum_kernel(const float* __restrict__ A_log,
                            const float* __restrict__ dt_bias) {
    int blk = blockIdx.x;
    int h = blk % Hh;
    int bc = blk / Hh;
    int b = bc / Nc, c = bc % Nc;
    int t = threadIdx.x;
    float A = -expf(A_log[h]);
    int bl = b * Ll + c * Ck + t;
    float raw = g_proj[(size_t)bl * ProjD + Inter + ConvD + h] + dt_bias[h];
    float dt = (raw > 20.f) ? raw : log1pf(expf(raw));
    g_dtv[(size_t)bl * Hh + h] = dt;
    float v = dt * A;
    __shared__ float s[Ck];
    s[t] = v;
    __syncthreads();
    for (int off = 1; off < Ck; off <<= 1) {
        float x = (t >= off) ? s[t - off] : 0.f;
        __syncthreads();
        s[t] += x;
        __syncthreads();
    }
    g_acum[(size_t)blk * Ck + t] = s[t];
}

// ---------------------------------------------------------------------------
// Gm[s,z] = sum_n C[s,n] * B[z,n] per (b,c), lower triangle (fp32 accum,
// fp16 g_convh inputs)
// ---------------------------------------------------------------------------
__global__ __launch_bounds__(256) void gm_kernel() {
    int bc = blockIdx.x;
    int sT = blockIdx.y, zT = blockIdx.z;
    if (zT > sT) return;
    int b = bc / Nc, c = bc % Nc;
    int rowbase = b * Ll + c * Ck;
    __shared__ __align__(16) float Cs[16][68];
    __shared__ __align__(16) float Bs[16][68];
    int tid = threadIdx.x;
    int ty = tid >> 4, tx = tid & 15;
    float acc[4][4];
#pragma unroll
    for (int i = 0; i < 4; i++)
#pragma unroll
        for (int j = 0; j < 4; j++) acc[i][j] = 0.f;

    int lrow = tid >> 2;
    int lcol = (tid & 3) * 4;

    for (int n0 = 0; n0 < Nn; n0 += 16) {
        const __half* pc = g_convh + (size_t)(rowbase + sT * 64 + lrow) * ConvD + Inter + Nn + n0 + lcol;
        const __half* pb = g_convh + (size_t)(rowbase + zT * 64 + lrow) * ConvD + Inter + n0 + lcol;
        float2 c01 = __half22float2(*(const half2*)pc);
        float2 c23 = __half22float2(*(const half2*)(pc + 2));
        float2 b01 = __half22float2(*(const half2*)pb);
        float2 b23 = __half22float2(*(const half2*)(pb + 2));
        Cs[lcol + 0][lrow] = c01.x; Cs[lcol + 1][lrow] = c01.y;
        Cs[lcol + 2][lrow] = c23.x; Cs[lcol + 3][lrow] = c23.y;
        Bs[lcol + 0][lrow] = b01.x; Bs[lcol + 1][lrow] = b01.y;
        Bs[lcol + 2][lrow] = b23.x; Bs[lcol + 3][lrow] = b23.y;
        __syncthreads();
#pragma unroll
        for (int kk = 0; kk < 16; kk++) {
            float4 rc = *(const float4*)&Cs[kk][ty * 4];
            float4 rb = *(const float4*)&Bs[kk][tx * 4];
            float rcv[4] = {rc.x, rc.y, rc.z, rc.w};
            float rbv[4] = {rb.x, rb.y, rb.z, rb.w};
#pragma unroll
            for (int i = 0; i < 4; i++)
#pragma unroll
                for (int j = 0; j < 4; j++) acc[i][j] += rcv[i] * rbv[j];
        }
        __syncthreads();
    }
#pragma unroll
    for (int i = 0; i < 4; i++) {
        int sg = sT * 64 + ty * 4 + i;
        float* pg = g_gm + ((size_t)bc * Ck + sg) * Ck + zT * 64 + tx * 4;
        *reinterpret_cast<float4*>(pg) = make_float4(acc[i][0], acc[i][1], acc[i][2], acc[i][3]);
    }
}

// ---------------------------------------------------------------------------
// states — fp16 mma: out[p=64][n=128] = sum_l H[p,l]*B[n,l], K=256 in 4 chunks.
// ---------------------------------------------------------------------------
__global__ __launch_bounds__(256) void states_kernel() {
    int bc = blockIdx.x, h = blockIdx.y;
    int b = bc / Nc, c = bc % Nc;
    int tid = threadIdx.x;
    int lane = tid & 31;
    int warp = tid >> 5;
    int wm = warp >> 1;   // 0..3
    int wn = warp & 1;    // 0..1

    __shared__ __align__(16) __half Hsh[64][72];    // [p][l]
    __shared__ __align__(16) __half Bsh[128][72];   // [n][l]

    const float* acumC = g_acum + ((size_t)bc * Hh + h) * Ck;
    float aLast = acumC[Ck - 1];
    int rowbase = b * Ll + c * Ck;

    float acc[8][4];
#pragma unroll
    for (int i = 0; i < 8; i++)
#pragma unroll
        for (int j = 0; j < 4; j++) acc[i][j] = 0.f;

    const unsigned hbv = su32(Hsh);
    const unsigned bbv = su32(Bsh);
    const int rA = lane & 15;
    const int cBy = (lane >> 4) << 4;

    for (int lc = 0; lc < 4; lc++) {
        {
            // Hsh[p][l] = hs[l][p] * dt[l] * exp(aLast - acum[l]) (transposed)
            int ll = tid >> 2;
            int p0 = (tid & 3) * 16;
            int l = rowbase + lc * 64 + ll;
            float w = g_dtv[(size_t)l * Hh + h] * expf(aLast - acumC[lc * 64 + ll]);
            const __half* ph = g_convh + (size_t)l * ConvD + h * Pp + p0;
#pragma unroll
            for (int u = 0; u < 8; u++) {
                float2 v = __half22float2(*(const half2*)(ph + u * 2));
                Hsh[p0 + u * 2 + 0][ll] = __float2half(v.x * w);
                Hsh[p0 + u * 2 + 1][ll] = __float2half(v.y * w);
            }
        }
#pragma unroll
        for (int i = 0; i < 8; i++) {
            // Bsh[n][l] = B[l][n] (transposed, direct half copy)
            int q = tid + (i << 8);
            int ll = q >> 5;
            int n4 = (q & 31) * 4;
            const __half* pb = g_convh + (size_t)(rowbase + lc * 64 + ll) * ConvD + Inter + n4;
            half2 b01 = *(const half2*)pb;
            half2 b23 = *(const half2*)(pb + 2);
            Bsh[n4 + 0][ll] = __low2half(b01);
            Bsh[n4 + 1][ll] = __high2half(b01);
            Bsh[n4 + 2][ll] = __low2half(b23);
            Bsh[n4 + 3][ll] = __high2half(b23);
        }
        __syncthreads();
#pragma unroll
        for (int ks = 0; ks < 4; ks++) {
            unsigned colb = (unsigned)(ks * 32 + cBy);
            unsigned a[4];
            ldsm4(a[0], a[1], a[2], a[3], hbv + (wm * 16 + rA) * 144 + colb);
            unsigned bfr[8][2];
#pragma unroll
            for (int nf2 = 0; nf2 < 4; nf2++) {
                unsigned rb = bbv + (wn * 64 + nf2 * 16 + rA) * 144 + colb;
                unsigned t0, t1, t2, t3;
                ldsm4(t0, t1, t2, t3, rb);
                bfr[nf2 * 2][0] = t0; bfr[nf2 * 2][1] = t2;
                bfr[nf2 * 2 + 1][0] = t1; bfr[nf2 * 2 + 1][1] = t3;
            }
#pragma unroll
            for (int nf = 0; nf < 8; nf++)
                mma16816(acc[nf], a, bfr[nf]);
        }
        __syncthreads();
    }

    float* ps = g_states + ((size_t)bc * Hh + h) * Pp * Nn;
    int g4 = lane >> 2, t4 = lane & 3;
    int p0r = wm * 16 + g4;
#pragma unroll
    for (int nf = 0; nf < 8; nf++) {
        int n = wn * 64 + nf * 8 + t4 * 2;
        *(float2*)(ps + (size_t)p0r * Nn + n) = make_float2(acc[nf][0], acc[nf][1]);
        *(float2*)(ps + (size_t)(p0r + 8) * Nn + n) = make_float2(acc[nf][2], acc[nf][3]);
    }
}

// ---------------------------------------------------------------------------
// Inter-chunk recurrence
// ---------------------------------------------------------------------------
__global__ void prev_kernel() {
    int idx = blockIdx.x * blockDim.x + threadIdx.x;
    if (idx >= Bb * Hh * Pp * Nn) return;
    int n = idx % Nn;
    int p = (idx / Nn) % Pp;
    int h = (idx / (Nn * Pp)) % Hh;
    int b = idx / (Nn * Pp * Hh);
    float r = 0.f;
    for (int c = 0; c < Nc; c++) {
        size_t off = (((size_t)(b * Nc + c) * Hh + h) * Pp + p) * Nn + n;
        g_prev[off] = r;
        float zl = g_acum[((size_t)(b * Nc + c) * Hh + h) * Ck + (Ck - 1)];
        r = g_states[off] + expf(zl) * r;
    }
}

// ---------------------------------------------------------------------------
// FUSED Y_diag + Y_off + D residual — tensor-core version (R14/R16 proven),
// now reading fp16 g_convh.
// ---------------------------------------------------------------------------
__global__ __launch_bounds__(256) void ydiag_yoff_kernel(const float* __restrict__ Dv) {
    int bc = blockIdx.x;
    int h = blockIdx.y;
    int sT = blockIdx.z;
    int b = bc / Nc, c = bc % Nc;
    int tid = threadIdx.x;
    int lane = tid & 31;
    int warp = tid >> 5;
    int wm = warp >> 1;     // 0..3 (16 rows each)
    int wn = warp & 1;      // 0..1 (32 cols each)

    __shared__ __align__(16) char sb[34816];
    __half* Msh = (__half*)sb;            // [64][72]  A: [s][z]
    __half* Hsh = (__half*)(sb + 9216);   // [64][72]  B: [p][z]
    __half* Csh = (__half*)sb;            // [64][136] A: [l][n]
    __half* Psh = (__half*)(sb + 17408);  // [64][136] B: [p][n]
    __shared__ float sAc[64], zAc[64], ezs[64];

    const float* acumC = g_acum + ((size_t)bc * Hh + h) * Ck;
    if (tid < 64) sAc[tid] = acumC[sT * 64 + tid];
    int rowbase = b * Ll + c * Ck;
    int lbase = rowbase + sT * 64;

    const unsigned mbase = su32(Msh);
    const unsigned hbase = su32(Hsh);
    const int rA = lane & 15;
    const int cBy = (lane >> 4) << 4;

    float accd[4][4];
#pragma unroll
    for (int i = 0; i < 4; i++)
#pragma unroll
        for (int j = 0; j < 4; j++) accd[i][j] = 0.f;

    for (int zT = 0; zT <= sT; zT++) {
        float M = acumC[zT * 64 + 63];
        if (tid < 64) {
            float az = acumC[zT * 64 + tid];
            zAc[tid] = az;
            ezs[tid] = expf(M - az);
        }
        {
            int zz = tid >> 2;
            int p0 = (tid & 3) * 16;
            int l = rowbase + zT * 64 + zz;
            float d = g_dtv[(size_t)l * Hh + h];
            const __half* ph = g_convh + (size_t)l * ConvD + h * Pp + p0;
#pragma unroll
            for (int u = 0; u < 8; u++) {
                float2 v = __half22float2(*(const half2*)(ph + u * 2));
                Hsh[(p0 + u * 2 + 0) * 72 + zz] = __float2half(v.x * d);
                Hsh[(p0 + u * 2 + 1) * 72 + zz] = __float2half(v.y * d);
            }
        }
        __syncthreads();
        {
            int zz4 = (tid & 15) * 4;
            int ss4 = (tid >> 4) * 4;
            if (zT < sT) {
#pragma unroll
                for (int a = 0; a < 4; a++) {
                    int ss = ss4 + a;
                    int sg = sT * 64 + ss;
                    float es = expf(sAc[ss] - M);
                    float4 g = ldg4(g_gm + ((size_t)bc * Ck + sg) * Ck + zT * 64 + zz4);
                    float m0 = g.x * ezs[zz4 + 0] * es;
                    float m1 = g.y * ezs[zz4 + 1] * es;
                    float m2 = g.z * ezs[zz4 + 2] * es;
                    float m3 = g.w * ezs[zz4 + 3] * es;
                    *(half2*)&Msh[ss * 72 + zz4]     = __floats2half2_rn(m0, m1);
                    *(half2*)&Msh[ss * 72 + zz4 + 2] = __floats2half2_rn(m2, m3);
                }
            } else {
#pragma unroll
                for (int a = 0; a < 4; a++) {
                    int ss = ss4 + a;
                    int sg = sT * 64 + ss;
                    float as = sAc[ss];
                    float4 g = ldg4(g_gm + ((size_t)bc * Ck + sg) * Ck + zT * 64 + zz4);
                    float gv[4] = {g.x, g.y, g.z, g.w};
                    float mv[4];
#pragma unroll
                    for (int q = 0; q < 4; q++) {
                        int zz = zz4 + q;
                        mv[q] = ((zT * 64 + zz) <= sg) ? gv[q] * expf(as - zAc[zz]) : 0.f;
                    }
                    *(half2*)&Msh[ss * 72 + zz4]     = __floats2half2_rn(mv[0], mv[1]);
                    *(half2*)&Msh[ss * 72 + zz4 + 2] = __floats2half2_rn(mv[2], mv[3]);
                }
            }
        }
        __syncthreads();
#pragma unroll
        for (int ks = 0; ks < 4; ks++) {
            unsigned colb = (unsigned)(ks * 32 + cBy);
            unsigned a[4];
            ldsm4(a[0], a[1], a[2], a[3], mbase + (wm * 16 + rA) * 144 + colb);
            unsigned bh[4][2];
#pragma unroll
            for (int nf2 = 0; nf2 < 2; nf2++) {
                unsigned rb = hbase + (wn * 32 + nf2 * 16 + rA) * 144 + colb;
                unsigned t0, t1, t2, t3;
                ldsm4(t0, t1, t2, t3, rb);
                bh[nf2 * 2][0] = t0; bh[nf2 * 2][1] = t2;
                bh[nf2 * 2 + 1][0] = t1; bh[nf2 * 2 + 1][1] = t3;
            }
#pragma unroll
            for (int nf = 0; nf < 4; nf++)
                mma16816(accd[nf], a, bh[nf]);
        }
        __syncthreads();
    }

    float acco[4][4];
#pragma unroll
    for (int i = 0; i < 4; i++)
#pragma unroll
        for (int j = 0; j < 4; j++) acco[i][j] = 0.f;

    const float* pprev = g_prev + ((size_t)bc * Hh + h) * Pp * Nn;
#pragma unroll
    for (int i = 0; i < 8; i++) {
        int q = tid + (i << 8);
        int row = q >> 5;
        int c4 = (q & 31) * 4;
        // Csh: direct fp16 copy (4 halfs = 8 bytes, aligned)
        *(uint2*)&Csh[row * 136 + c4] =
            *(const uint2*)(g_convh + (size_t)(lbase + row) * ConvD + Inter + Nn + c4);
        float4 vp = ldg4(pprev + (size_t)row * Nn + c4);
        *(half2*)&Psh[row * 136 + c4]     = __floats2half2_rn(vp.x, vp.y);
        *(half2*)&Psh[row * 136 + c4 + 2] = __floats2half2_rn(vp.z, vp.w);
    }
    __syncthreads();
    const unsigned cbase2 = su32(Csh);
    const unsigned pbase2 = su32(Psh);
#pragma unroll
    for (int ks = 0; ks < 8; ks++) {
        unsigned colb = (unsigned)(ks * 32 + cBy);
        unsigned a[4];
        ldsm4(a[0], a[1], a[2], a[3], cbase2 + (wm * 16 + rA) * 272 + colb);
        unsigned bh[4][2];
#pragma unroll
        for (int nf2 = 0; nf2 < 2; nf2++) {
            unsigned rb = pbase2 + (wn * 32 + nf2 * 16 + rA) * 272 + colb;
            unsigned t0, t1, t2, t3;
            ldsm4(t0, t1, t2, t3, rb);
            bh[nf2 * 2][0] = t0; bh[nf2 * 2][1] = t2;
            bh[nf2 * 2 + 1][0] = t1; bh[nf2 * 2 + 1][1] = t3;
        }
#pragma unroll
        for (int nf = 0; nf < 4; nf++)
            mma16816(acco[nf], a, bh[nf]);
    }

    float Dh = Dv[h];
    int r0 = wm * 16 + (lane >> 2);
    int pb0 = wn * 32 + (lane & 3) * 2;
    float sd0 = expf(sAc[r0]);
    float sd1 = expf(sAc[r0 + 8]);
    int l0v = lbase + r0;
    int l1v = l0v + 8;
#pragma unroll
    for (int nf = 0; nf < 4; nf++) {
        int p = pb0 + nf * 8;
        float2 hv0 = __half22float2(*(const half2*)(g_convh + (size_t)l0v * ConvD + h * Pp + p));
        float2 o0;
        o0.x = accd[nf][0] + acco[nf][0] * sd0 + Dh * hv0.x;
        o0.y = accd[nf][1] + acco[nf][1] * sd0 + Dh * hv0.y;
        *(float2*)(g_y + (size_t)l0v * Inter + h * Pp + p) = o0;
        float2 hv1 = __half22float2(*(const half2*)(g_convh + (size_t)l1v * ConvD + h * Pp + p));
        float2 o1;
        o1.x = accd[nf][2] + acco[nf][2] * sd1 + Dh * hv1.x;
        o1.y = accd[nf][3] + acco[nf][3] * sd1 + Dh * hv1.y;
        *(float2*)(g_y + (size_t)l1v * Inter + h * Pp + p) = o1;
    }
}

// ---------------------------------------------------------------------------
// Gated RMSNorm; writes fp16-rounded y for the 1-pass out-proj
// ---------------------------------------------------------------------------
__global__ __launch_bounds__(256) void norm_kernel(const float* __restrict__ norm_w) {
    int row = blockIdx.x;
    int tid = threadIdx.x;
    const float* pg = g_proj + (size_t)row * ProjD;
    const float* py = g_y + (size_t)row * Inter;
    float f[8];
    float ss = 0.f;
#pragma unroll
    for (int u = 0; u < 8; u++) {
        int i = tid + u * 256;
        float g = pg[i];
        float v = py[i] * siluf(g);
        f[u] = v;
        ss += v * v;
    }
    __shared__ float red[8];
    int lane = tid & 31, wid = tid >> 5;
#pragma unroll
    for (int o = 16; o > 0; o >>= 1) ss += __shfl_xor_sync(0xffffffffu, ss, o);
    if (lane == 0) red[wid] = ss;
    __syncthreads();
    if (tid == 0) {
        float t = 0.f;
#pragma unroll
        for (int i = 0; i < 8; i++) t += red[i];
        red[0] = t;
    }
    __syncthreads();
    float rs = rsqrtf(red[0] / (float)Inter + 1e-6f);
#pragma unroll
    for (int u = 0; u < 8; u++) {
        int i = tid + u * 256;
        float v = f[u] * rs * norm_w[i];
        g_Ah[(size_t)row * Inter + i] = __float2half(v);
    }
}

// ---------------------------------------------------------------------------
// Launch
// ---------------------------------------------------------------------------
extern "C" void kernel_launch(void* const* d_in, const int* in_sizes, int n_in,
                              void* d_out, int out_size) {
    const float* x         = (const float*)d_in[0];
    const float* in_proj_w = (const float*)d_in[1];
    const float* conv_w    = (const float*)d_in[2];
    const float* conv_b    = (const float*)d_in[3];
    const float* dt_bias   = (const float*)d_in[4];
    const float* A_log     = (const float*)d_in[5];
    const float* Dv        = (const float*)d_in[6];
    const float* norm_w    = (const float*)d_in[7];
    const float* out_proj_w= (const float*)d_in[8];
    float* out = (float*)d_out;

    cudaFuncSetAttribute(gemm_in_kernel, cudaFuncAttributeMaxDynamicSharedMemorySize, GEMM_SMEM);
    cudaFuncSetAttribute(gemm_out_kernel, cudaFuncAttributeMaxDynamicSharedMemorySize, GEMM_SMEM);

    // 1) round x and in_proj_w to fp16
    {
        int n = BL * Dm;
        round_x_kernel<<<(n + 255) / 256, 256>>>(x, n);
        n = ProjD * Dm;
        round_w_kernel<<<(n + 255) / 256, 256>>>(in_proj_w, n);
    }
    // 2) in-projection GEMM (1-pass fp16)
    {
        dim3 grid((ProjD + 127) / 128, BL / 128);
        gemm_in_kernel<<<grid, 256, GEMM_SMEM>>>();
    }
    // 3) conv + SiLU (fp16 output)
    {
        dim3 grid(ConvD / 256, Ll / 32, Bb);
        conv_silu_kernel<<<grid, 256>>>(conv_w, conv_b);
    }
    // 4) cumsum of dt*A (fused softplus)
    acum_kernel<<<Bb * Nc * Hh, Ck>>>(A_log, dt_bias);
    // 5) Gm = C B^T
    {
        dim3 grid(Bb * Nc, Ck / 64, Ck / 64);
        gm_kernel<<<grid, 256>>>();
    }
    // 6) states (fp16 mma)
    {
        dim3 grid(Bb * Nc, Hh);
        states_kernel<<<grid, 256>>>();
    }
    // 7) inter-chunk recurrence
    {
        int total = Bb * Hh * Pp * Nn;
        prev_kernel<<<(total + 255) / 256, 256>>>();
    }
    // 8) fused Y_diag + Y_off + D residual (tensor cores)
    {
        dim3 grid(Bb * Nc, Hh, Ck / 64);
        ydiag_yoff_kernel<<<grid, 256>>>(Dv);
    }
    // 9) gated RMSNorm (writes fp16 y)
    norm_kernel<<<BL, 256>>>(norm_w);
    // 10) round out_proj_w to fp16
    {
        int n = Dm * Inter;
        round_w_kernel<<<(n + 255) / 256, 256>>>(out_proj_w, n);
    }
    // 11) out-projection GEMM (1-pass fp16)
    {
        dim3 grid(Dm / 128, BL / 128);
        gemm_out_kernel<<<grid, 256, GEMM_SMEM>>>(out);
    }
    (void)in_sizes; (void)n_in; (void)out_size;
}